// round 16
// baseline (speedup 1.0000x reference)
#include <cuda_runtime.h>
#include <cuda_fp16.h>
#include <cstdint>

// Problem constants
#define B_SZ   4096
#define F_SZ   100
#define H_SZ   128
#define H2_SZ  64
#define T_SZ   2

// Tiling: 2 independent 128-thread groups per CTA; each group: 128 rows x 1 feature
// Each warp carries TWO m16 A-tiles (32 rows) -> 1 LDS.128 feeds 4 HMMAs.
#define TB      128     // batch rows per CTA (shared by both groups)
#define NSTEP   3
#define THREADS 256
#define GT      128     // threads per group
#define WB32    8192    // uint32 entries per packed 32KB fp16 weight matrix

// Fragment-PAIR-packed fp16 weights: [layer][f][8192] uint32 (f16x2)
// For (ks, nt, lane): offset = ks*1024 + (nt>>1)*128 + lane*4 + (nt&1)*2
__device__ uint32_t g_wp[3][F_SZ][WB32];
// Collapsed head
__device__ float g_wv[F_SZ * T_SZ * H_SZ];
__device__ float g_c[F_SZ * T_SZ];

// ---------------- scalar helpers ----------------
__device__ __forceinline__ float elu_f(float v) {
    return v > 0.0f ? v : (__expf(v) - 1.0f);
}
__device__ __forceinline__ uint32_t pack2h(float v0, float v1) {
    uint32_t p;
    asm("cvt.rn.f16x2.f32 %0, %1, %2;" : "=r"(p) : "f"(v1), "f"(v0));
    return p;
}
// no-return vector fp32 reduction to gmem (8B-aligned addr)
__device__ __forceinline__ void red2(float* addr, float v0, float v1) {
    asm volatile("red.global.add.v2.f32 [%0], {%1, %2};"
                 :: "l"(addr), "f"(v0), "f"(v1) : "memory");
}

// mma.sync m16n8k16 fp16 -> fp32
__device__ __forceinline__ void mma16816(float d[4], const uint32_t a[4],
                                         uint32_t b0, uint32_t b1) {
    asm("mma.sync.aligned.m16n8k16.row.col.f32.f16.f16.f32 "
        "{%0,%1,%2,%3}, {%4,%5,%6,%7}, {%8,%9}, {%0,%1,%2,%3};"
        : "+f"(d[0]), "+f"(d[1]), "+f"(d[2]), "+f"(d[3])
        : "r"(a[0]), "r"(a[1]), "r"(a[2]), "r"(a[3]), "r"(b0), "r"(b1));
}

// ---------------- cp.async ----------------
__device__ __forceinline__ void cp16(uint32_t saddr, const void* g) {
    asm volatile("cp.async.cg.shared.global [%0], [%1], 16;\n" :: "r"(saddr), "l"(g));
}
__device__ __forceinline__ void cp_commit() {
    asm volatile("cp.async.commit_group;\n" ::: "memory");
}
__device__ __forceinline__ void cp_wait0() {
    asm volatile("cp.async.wait_group 0;\n" ::: "memory");
}
__device__ __forceinline__ void cp_wait1() {
    asm volatile("cp.async.wait_group 1;\n" ::: "memory");
}
// copy one 32KB packed weight matrix with 128 group threads (16 x 16B each)
__device__ __forceinline__ void issue_w(uint32_t sdst, const char* gsrc, int gt) {
#pragma unroll
    for (int i = 0; i < 16; i++) {
        int b = (gt + i * GT) * 16;
        cp16(sdst + b, gsrc + b);
    }
    cp_commit();
}

// ---------------- setup: pack weights, head collapse, zero out ----------------
__global__ void nam_setup(float* __restrict__ out, int n_out,
                          const float* __restrict__ W2, const float* __restrict__ W3,
                          const float* __restrict__ W4,
                          const float* __restrict__ Wh1, const float* __restrict__ bh1,
                          const float* __restrict__ Wh2, const float* __restrict__ bh2) {
    const int blk = blockIdx.x;
    const int tid = threadIdx.x;
    if (blk < 3 * F_SZ) {
        const int l = blk / F_SZ, f = blk % F_SZ;
        const float* W = (l == 0 ? W2 : (l == 1 ? W3 : W4)) + (long)f * H_SZ * H_SZ;
        uint32_t* hi = &g_wp[l][f][0];
        for (int e = tid; e < 4096; e += THREADS) {
            const int lane = e & 31;
            const int t = lane & 3, g = lane >> 2;
            const int nt = (e >> 5) & 15, ks = e >> 9;
            const int n = nt * 8 + g;
            const int k0 = ks * 16 + t * 2;
            float w00 = W[(k0)     * H_SZ + n];
            float w01 = W[(k0 + 1) * H_SZ + n];
            float w10 = W[(k0 + 8) * H_SZ + n];
            float w11 = W[(k0 + 9) * H_SZ + n];
            const int base = ks * 1024 + (nt >> 1) * 128 + lane * 4 + (nt & 1) * 2;
            hi[base]     = pack2h(w00, w01);
            hi[base + 1] = pack2h(w10, w11);
        }
    } else if (blk < 3 * F_SZ + F_SZ * T_SZ) {
        const int ft = blk - 3 * F_SZ;
        __shared__ float s2[H2_SZ];
        if (tid < H2_SZ) s2[tid] = Wh2[ft * H2_SZ + tid];
        __syncthreads();
        if (tid < H_SZ) {
            const float* wp = Wh1 + ((long)ft * H_SZ + tid) * H2_SZ;
            float s = 0.0f;
#pragma unroll 8
            for (int m = 0; m < H2_SZ; m++) s += wp[m] * s2[m];
            g_wv[ft * H_SZ + tid] = s;
            if (tid == 0) {
                float cc = bh2[ft];
                const float* bp = bh1 + ft * H2_SZ;
                for (int m = 0; m < H2_SZ; m++) cc += bp[m] * s2[m];
                g_c[ft] = cc;
            }
        }
    } else {
        int i = (blk - (3 * F_SZ + F_SZ * T_SZ)) * THREADS + tid;
        if (i < n_out) out[i] = 0.0f;
    }
}

// ---------------- fused main kernel ----------------
// smem: per group 2 x 32KB ring (gid*65536); 2 groups = 128KB; + 2 small areas
#define FS_OFF  131072
#define GF      1152     // floats of small area per group
#define SX_I    0        // 128
#define SW1_I   128      // 128
#define SB1_I   256      // 128
#define SBIAS_I 384      // 384 (b2|b3|b4)
#define SWV_I   768      // 256
#define SC_I    1024     // 2
#define SMEM_BYTES (FS_OFF + 2 * GF * 4)

#define GBAR() asm volatile("bar.sync %0, 128;" :: "r"(gid + 1) : "memory")

__global__ void __launch_bounds__(THREADS, 1)
nam_main(const float* __restrict__ x, const int* __restrict__ a,
         const float* __restrict__ W1, const float* __restrict__ b1,
         const float* __restrict__ b2, const float* __restrict__ b3,
         const float* __restrict__ b4, float* __restrict__ out) {
    extern __shared__ char smem[];

    const int tid = threadIdx.x;
    const int gid = tid >> 7;        // group 0/1
    const int gt  = tid & 127;       // thread within group
    const int w4 = gt >> 5, lane = gt & 31;
    const int t = lane & 3, g = lane >> 2;
    const int t2 = t * 2;
    const int r0 = 32 * w4 + g;      // tile0 rows: r0, r0+8; tile1: r0+16, r0+24
    const int b0 = blockIdx.x * TB;
    const int f = blockIdx.y * 2 + gid;    // one feature per group
    const int gr0 = b0 + r0;

    float* fs  = (float*)(smem + FS_OFF) + gid * GF;
    float* sx    = fs + SX_I;
    float* sw1   = fs + SW1_I;
    float* sb1   = fs + SB1_I;
    float* sbias = fs + SBIAS_I;
    float* swv   = fs + SWV_I;
    float* sc    = fs + SC_I;

    const uint32_t smem_u32 = (uint32_t)__cvta_generic_to_shared(smem);
    const uint32_t wgbase = smem_u32 + (uint32_t)gid * 65536u;   // 2 x 32KB ring
    const char* const wgen = smem + gid * 65536;

    // treatments for this thread's 4 rows
    const int ta0 = a[gr0],      ta1 = a[gr0 + 8];
    const int ta2 = a[gr0 + 16], ta3 = a[gr0 + 24];

    uint32_t Ah[2][8][4];
    float y0 = 0.f, y1 = 0.f, y2 = 0.f, y3 = 0.f;

    // prologue: W2 -> slot0, W3 -> slot1
    issue_w(wgbase,          (const char*)&g_wp[0][f][0], gt);
    issue_w(wgbase + 32768u, (const char*)&g_wp[1][f][0], gt);

    // per-feature small loads (once; one feature per group)
    sx[gt]          = x[(long)(b0 + gt) * F_SZ + f];
    sw1[gt]         = W1[f * H_SZ + gt];
    sb1[gt]         = b1[f * H_SZ + gt];
    sbias[gt]       = b2[f * H_SZ + gt];
    sbias[128 + gt] = b3[f * H_SZ + gt];
    sbias[256 + gt] = b4[f * H_SZ + gt];
    swv[gt]       = g_wv[f * 256 + gt];
    swv[128 + gt] = g_wv[f * 256 + 128 + gt];
    if (gt < 2) sc[gt] = g_c[f * 2 + gt];
    GBAR();

    // ---- layer 1: build fp16 A-fragments for both tiles ----
    {
        const float xv0 = sx[r0],      xv1 = sx[r0 + 8];
        const float xv2 = sx[r0 + 16], xv3 = sx[r0 + 24];
#pragma unroll
        for (int kk = 0; kk < 8; kk++) {
            const int cA = 16 * kk + t2, cB = cA + 8;
            float2 wA = *(const float2*)&sw1[cA];
            float2 bA = *(const float2*)&sb1[cA];
            float2 wB = *(const float2*)&sw1[cB];
            float2 bB = *(const float2*)&sb1[cB];
            Ah[0][kk][0] = pack2h(elu_f(xv0 * wA.x + bA.x),
                                  elu_f(xv0 * wA.y + bA.y));
            Ah[0][kk][1] = pack2h(elu_f(xv1 * wA.x + bA.x),
                                  elu_f(xv1 * wA.y + bA.y));
            Ah[0][kk][2] = pack2h(elu_f(xv0 * wB.x + bB.x),
                                  elu_f(xv0 * wB.y + bB.y));
            Ah[0][kk][3] = pack2h(elu_f(xv1 * wB.x + bB.x),
                                  elu_f(xv1 * wB.y + bB.y));
            Ah[1][kk][0] = pack2h(elu_f(xv2 * wA.x + bA.x),
                                  elu_f(xv2 * wA.y + bA.y));
            Ah[1][kk][1] = pack2h(elu_f(xv3 * wA.x + bA.x),
                                  elu_f(xv3 * wA.y + bA.y));
            Ah[1][kk][2] = pack2h(elu_f(xv2 * wB.x + bB.x),
                                  elu_f(xv2 * wB.y + bB.y));
            Ah[1][kk][3] = pack2h(elu_f(xv3 * wB.x + bB.x),
                                  elu_f(xv3 * wB.y + bB.y));
        }
    }

#pragma unroll 1
    for (int l = 0; l < NSTEP; l++) {
        if (l < 2) cp_wait1(); else cp_wait0();
        GBAR();   // slots: l=0 ->0, l=1 ->1, l=2 ->0

        const uint32_t* Wh =
            (const uint32_t*)(wgen + (l == 1 ? 32768 : 0)) + lane * 4;

        // ---- full-N accumulators, bias-initialized ----
        float acc[2][16][4];
        {
            const float* sb = sbias + l * 128;
#pragma unroll
            for (int nt = 0; nt < 16; nt++) {
                float2 b = *(const float2*)&sb[8 * nt + t2];
                acc[0][nt][0] = b.x; acc[0][nt][1] = b.y;
                acc[0][nt][2] = b.x; acc[0][nt][3] = b.y;
                acc[1][nt][0] = b.x; acc[1][nt][1] = b.y;
                acc[1][nt][2] = b.x; acc[1][nt][3] = b.y;
            }
        }

        // ---- GEMM: 64 LDS.128, software-pipelined, 4 HMMAs per load ----
        {
            uint4 w = *(const uint4*)(Wh);
#pragma unroll
            for (int q = 0; q < 64; q++) {
                const int ks = q >> 3, p = q & 7;
                uint4 wn;
                if (q < 63) {
                    const int q1 = q + 1;
                    wn = *(const uint4*)(Wh + (q1 >> 3) * 1024 + (q1 & 7) * 128);
                }
                mma16816(acc[0][2 * p],     Ah[0][ks], w.x, w.y);
                mma16816(acc[0][2 * p + 1], Ah[0][ks], w.z, w.w);
                mma16816(acc[1][2 * p],     Ah[1][ks], w.x, w.y);
                mma16816(acc[1][2 * p + 1], Ah[1][ks], w.z, w.w);
                w = wn;
            }
        }

        GBAR();   // all group threads done reading the ring slot

        if (l == 0)   // prefetch W4 into slot0 (just released); overlaps epilogue
            issue_w(wgbase, (const char*)&g_wp[2][f][0], gt);

        if (l < 2) {
            // ---- epilogue: ELU + fp16 pack, written in place into Ah ----
#pragma unroll
            for (int kk = 0; kk < 8; kk++) {
                const int nt0 = 2 * kk, nt1 = 2 * kk + 1;
#pragma unroll
                for (int m = 0; m < 2; m++) {
                    Ah[m][kk][0] = pack2h(elu_f(acc[m][nt0][0]),
                                          elu_f(acc[m][nt0][1]));
                    Ah[m][kk][1] = pack2h(elu_f(acc[m][nt0][2]),
                                          elu_f(acc[m][nt0][3]));
                    Ah[m][kk][2] = pack2h(elu_f(acc[m][nt1][0]),
                                          elu_f(acc[m][nt1][1]));
                    Ah[m][kk][3] = pack2h(elu_f(acc[m][nt1][2]),
                                          elu_f(acc[m][nt1][3]));
                }
            }
        } else {
            // ---- layer-4 epilogue: backbone reduction + collapsed head ----
#pragma unroll
            for (int nt = 0; nt < 16; nt++) {
                const int col = 8 * nt + t2;
                float a00 = acc[0][nt][0], a01 = acc[0][nt][1];
                float a10 = acc[0][nt][2], a11 = acc[0][nt][3];
                float a20 = acc[1][nt][0], a21 = acc[1][nt][1];
                float a30 = acc[1][nt][2], a31 = acc[1][nt][3];
                red2(&out[(long)(gr0)      * H_SZ + col], a00, a01);
                red2(&out[(long)(gr0 + 8)  * H_SZ + col], a10, a11);
                red2(&out[(long)(gr0 + 16) * H_SZ + col], a20, a21);
                red2(&out[(long)(gr0 + 24) * H_SZ + col], a30, a31);
                float2 wv0 = *(const float2*)&swv[ta0 * H_SZ + col];
                float2 wv1 = *(const float2*)&swv[ta1 * H_SZ + col];
                float2 wv2 = *(const float2*)&swv[ta2 * H_SZ + col];
                float2 wv3 = *(const float2*)&swv[ta3 * H_SZ + col];
                y0 += a00 * wv0.x + a01 * wv0.y;
                y1 += a10 * wv1.x + a11 * wv1.y;
                y2 += a20 * wv2.x + a21 * wv2.y;
                y3 += a30 * wv3.x + a31 * wv3.y;
            }
        }
    }

    // ---- finale: head outputs ----
    y0 += __shfl_xor_sync(0xffffffffu, y0, 1);
    y0 += __shfl_xor_sync(0xffffffffu, y0, 2);
    y1 += __shfl_xor_sync(0xffffffffu, y1, 1);
    y1 += __shfl_xor_sync(0xffffffffu, y1, 2);
    y2 += __shfl_xor_sync(0xffffffffu, y2, 1);
    y2 += __shfl_xor_sync(0xffffffffu, y2, 2);
    y3 += __shfl_xor_sync(0xffffffffu, y3, 1);
    y3 += __shfl_xor_sync(0xffffffffu, y3, 2);
    if (t == 0) {
        atomicAdd(&out[B_SZ * H_SZ + gr0],      y0 + sc[ta0]);
        atomicAdd(&out[B_SZ * H_SZ + gr0 + 8],  y1 + sc[ta1]);
        atomicAdd(&out[B_SZ * H_SZ + gr0 + 16], y2 + sc[ta2]);
        atomicAdd(&out[B_SZ * H_SZ + gr0 + 24], y3 + sc[ta3]);
    }
}

// ---------------- launch ----------------
extern "C" void kernel_launch(void* const* d_in, const int* in_sizes, int n_in,
                              void* d_out, int out_size) {
    const float* x   = (const float*)d_in[0];
    const int*   a   = (const int*)d_in[1];
    const float* W1  = (const float*)d_in[2];
    const float* b1  = (const float*)d_in[3];
    const float* W2  = (const float*)d_in[4];
    const float* b2  = (const float*)d_in[5];
    const float* W3  = (const float*)d_in[6];
    const float* b3  = (const float*)d_in[7];
    const float* W4  = (const float*)d_in[8];
    const float* b4  = (const float*)d_in[9];
    const float* Wh1 = (const float*)d_in[10];
    const float* bh1 = (const float*)d_in[11];
    const float* Wh2 = (const float*)d_in[12];
    const float* bh2 = (const float*)d_in[13];
    float* out = (float*)d_out;

    cudaFuncSetAttribute(nam_main, cudaFuncAttributeMaxDynamicSharedMemorySize,
                         SMEM_BYTES);

    const int zero_blocks = (out_size + THREADS - 1) / THREADS;
    nam_setup<<<3 * F_SZ + F_SZ * T_SZ + zero_blocks, THREADS>>>(
        out, out_size, W2, W3, W4, Wh1, bh1, Wh2, bh2);

    dim3 grid(B_SZ / TB, F_SZ / 2);
    nam_main<<<grid, THREADS, SMEM_BYTES>>>(x, a, W1, b1, b2, b3, b4, out);
}

// round 17
// speedup vs baseline: 1.1478x; 1.1478x over previous
#include <cuda_runtime.h>
#include <cuda_fp16.h>
#include <cstdint>

// Problem constants
#define B_SZ   4096
#define F_SZ   100
#define H_SZ   128
#define H2_SZ  64
#define T_SZ   2

// Tiling: 2 independent 128-thread groups per CTA; each group: 128 rows x 1 feature
// Each warp carries TWO m16 A-tiles (32 rows) -> 1 LDS.128 feeds 4 HMMAs.
#define TB      128     // batch rows per CTA (shared by both groups)
#define NSTEP   3
#define THREADS 256
#define GT      128     // threads per group
#define WB32    8192    // uint32 entries per packed 32KB fp16 weight matrix

// Fragment-PAIR-packed fp16 weights: [layer][f][8192] uint32 (f16x2)
// For (ks, nt, lane): offset = ks*1024 + (nt>>1)*128 + lane*4 + (nt&1)*2
__device__ uint32_t g_wp[3][F_SZ][WB32];
// Collapsed head
__device__ float g_wv[F_SZ * T_SZ * H_SZ];
__device__ float g_c[F_SZ * T_SZ];

// ---------------- scalar helpers ----------------
__device__ __forceinline__ float elu_f(float v) {
    return v > 0.0f ? v : (__expf(v) - 1.0f);
}
__device__ __forceinline__ uint32_t pack2h(float v0, float v1) {
    uint32_t p;
    asm("cvt.rn.f16x2.f32 %0, %1, %2;" : "=r"(p) : "f"(v1), "f"(v0));
    return p;
}
// no-return vector fp32 reduction to gmem (8B-aligned addr)
__device__ __forceinline__ void red2(float* addr, float v0, float v1) {
    asm volatile("red.global.add.v2.f32 [%0], {%1, %2};"
                 :: "l"(addr), "f"(v0), "f"(v1) : "memory");
}

// mma.sync m16n8k16 fp16 -> fp32
__device__ __forceinline__ void mma16816(float d[4], const uint32_t a[4],
                                         uint32_t b0, uint32_t b1) {
    asm("mma.sync.aligned.m16n8k16.row.col.f32.f16.f16.f32 "
        "{%0,%1,%2,%3}, {%4,%5,%6,%7}, {%8,%9}, {%0,%1,%2,%3};"
        : "+f"(d[0]), "+f"(d[1]), "+f"(d[2]), "+f"(d[3])
        : "r"(a[0]), "r"(a[1]), "r"(a[2]), "r"(a[3]), "r"(b0), "r"(b1));
}

// ---------------- cp.async ----------------
__device__ __forceinline__ void cp16(uint32_t saddr, const void* g) {
    asm volatile("cp.async.cg.shared.global [%0], [%1], 16;\n" :: "r"(saddr), "l"(g));
}
__device__ __forceinline__ void cp_commit() {
    asm volatile("cp.async.commit_group;\n" ::: "memory");
}
__device__ __forceinline__ void cp_wait0() {
    asm volatile("cp.async.wait_group 0;\n" ::: "memory");
}
__device__ __forceinline__ void cp_wait1() {
    asm volatile("cp.async.wait_group 1;\n" ::: "memory");
}
// copy one 32KB packed weight matrix with 128 group threads (16 x 16B each)
__device__ __forceinline__ void issue_w(uint32_t sdst, const char* gsrc, int gt) {
#pragma unroll
    for (int i = 0; i < 16; i++) {
        int b = (gt + i * GT) * 16;
        cp16(sdst + b, gsrc + b);
    }
    cp_commit();
}

// ---------------- setup: pack weights, head collapse, zero out ----------------
__global__ void nam_setup(float* __restrict__ out, int n_out,
                          const float* __restrict__ W2, const float* __restrict__ W3,
                          const float* __restrict__ W4,
                          const float* __restrict__ Wh1, const float* __restrict__ bh1,
                          const float* __restrict__ Wh2, const float* __restrict__ bh2) {
    const int blk = blockIdx.x;
    const int tid = threadIdx.x;
    if (blk < 3 * F_SZ) {
        const int l = blk / F_SZ, f = blk % F_SZ;
        const float* W = (l == 0 ? W2 : (l == 1 ? W3 : W4)) + (long)f * H_SZ * H_SZ;
        uint32_t* hi = &g_wp[l][f][0];
        for (int e = tid; e < 4096; e += THREADS) {
            const int lane = e & 31;
            const int t = lane & 3, g = lane >> 2;
            const int nt = (e >> 5) & 15, ks = e >> 9;
            const int n = nt * 8 + g;
            const int k0 = ks * 16 + t * 2;
            float w00 = W[(k0)     * H_SZ + n];
            float w01 = W[(k0 + 1) * H_SZ + n];
            float w10 = W[(k0 + 8) * H_SZ + n];
            float w11 = W[(k0 + 9) * H_SZ + n];
            const int base = ks * 1024 + (nt >> 1) * 128 + lane * 4 + (nt & 1) * 2;
            hi[base]     = pack2h(w00, w01);
            hi[base + 1] = pack2h(w10, w11);
        }
    } else if (blk < 3 * F_SZ + F_SZ * T_SZ) {
        const int ft = blk - 3 * F_SZ;
        __shared__ float s2[H2_SZ];
        if (tid < H2_SZ) s2[tid] = Wh2[ft * H2_SZ + tid];
        __syncthreads();
        if (tid < H_SZ) {
            const float* wp = Wh1 + ((long)ft * H_SZ + tid) * H2_SZ;
            float s = 0.0f;
#pragma unroll 8
            for (int m = 0; m < H2_SZ; m++) s += wp[m] * s2[m];
            g_wv[ft * H_SZ + tid] = s;
            if (tid == 0) {
                float cc = bh2[ft];
                const float* bp = bh1 + ft * H2_SZ;
                for (int m = 0; m < H2_SZ; m++) cc += bp[m] * s2[m];
                g_c[ft] = cc;
            }
        }
    } else {
        int i = (blk - (3 * F_SZ + F_SZ * T_SZ)) * THREADS + tid;
        if (i < n_out) out[i] = 0.0f;
    }
}

// ---------------- fused main kernel ----------------
// smem: per group 2 x 32KB ring (gid*65536); 2 groups = 128KB; + 2 small areas
#define FS_OFF  131072
#define GF      1152     // floats of small area per group
#define SX_I    0        // 128
#define SW1_I   128      // 128
#define SB1_I   256      // 128
#define SBIAS_I 384      // 384 (b2|b3|b4)
#define SWV_I   768      // 256
#define SC_I    1024     // 2
#define SMEM_BYTES (FS_OFF + 2 * GF * 4)

#define GBAR() asm volatile("bar.sync %0, 128;" :: "r"(gid + 1) : "memory")

__global__ void __launch_bounds__(THREADS, 1)
nam_main(const float* __restrict__ x, const int* __restrict__ a,
         const float* __restrict__ W1, const float* __restrict__ b1,
         const float* __restrict__ b2, const float* __restrict__ b3,
         const float* __restrict__ b4, float* __restrict__ out) {
    extern __shared__ char smem[];

    const int tid = threadIdx.x;
    const int gid = tid >> 7;        // group 0/1
    const int gt  = tid & 127;       // thread within group
    const int w4 = gt >> 5, lane = gt & 31;
    const int t = lane & 3, g = lane >> 2;
    const int t2 = t * 2;
    const int r0 = 32 * w4 + g;      // tile0 rows: r0, r0+8; tile1: r0+16, r0+24
    const int b0 = blockIdx.x * TB;
    const int f = blockIdx.y * 2 + gid;    // one feature per group
    const int gr0 = b0 + r0;

    float* fs  = (float*)(smem + FS_OFF) + gid * GF;
    float* sx    = fs + SX_I;
    float* sw1   = fs + SW1_I;
    float* sb1   = fs + SB1_I;
    float* sbias = fs + SBIAS_I;
    float* swv   = fs + SWV_I;
    float* sc    = fs + SC_I;

    const uint32_t smem_u32 = (uint32_t)__cvta_generic_to_shared(smem);
    const uint32_t wgbase = smem_u32 + (uint32_t)gid * 65536u;   // 2 x 32KB ring
    const char* const wgen = smem + gid * 65536;

    // treatments for this thread's 4 rows
    const int ta0 = a[gr0],      ta1 = a[gr0 + 8];
    const int ta2 = a[gr0 + 16], ta3 = a[gr0 + 24];

    uint32_t Ah[2][8][4];
    float y0 = 0.f, y1 = 0.f, y2 = 0.f, y3 = 0.f;

    // prologue: W2 -> slot0, W3 -> slot1
    issue_w(wgbase,          (const char*)&g_wp[0][f][0], gt);
    issue_w(wgbase + 32768u, (const char*)&g_wp[1][f][0], gt);

    // per-feature small loads (once; one feature per group)
    sx[gt]          = x[(long)(b0 + gt) * F_SZ + f];
    sw1[gt]         = W1[f * H_SZ + gt];
    sb1[gt]         = b1[f * H_SZ + gt];
    sbias[gt]       = b2[f * H_SZ + gt];
    sbias[128 + gt] = b3[f * H_SZ + gt];
    sbias[256 + gt] = b4[f * H_SZ + gt];
    swv[gt]       = g_wv[f * 256 + gt];
    swv[128 + gt] = g_wv[f * 256 + 128 + gt];
    if (gt < 2) sc[gt] = g_c[f * 2 + gt];
    GBAR();

    // ---- layer 1: build fp16 A-fragments for both tiles ----
    {
        const float xv0 = sx[r0],      xv1 = sx[r0 + 8];
        const float xv2 = sx[r0 + 16], xv3 = sx[r0 + 24];
#pragma unroll
        for (int kk = 0; kk < 8; kk++) {
            const int cA = 16 * kk + t2, cB = cA + 8;
            float2 wA = *(const float2*)&sw1[cA];
            float2 bA = *(const float2*)&sb1[cA];
            float2 wB = *(const float2*)&sw1[cB];
            float2 bB = *(const float2*)&sb1[cB];
            Ah[0][kk][0] = pack2h(elu_f(xv0 * wA.x + bA.x),
                                  elu_f(xv0 * wA.y + bA.y));
            Ah[0][kk][1] = pack2h(elu_f(xv1 * wA.x + bA.x),
                                  elu_f(xv1 * wA.y + bA.y));
            Ah[0][kk][2] = pack2h(elu_f(xv0 * wB.x + bB.x),
                                  elu_f(xv0 * wB.y + bB.y));
            Ah[0][kk][3] = pack2h(elu_f(xv1 * wB.x + bB.x),
                                  elu_f(xv1 * wB.y + bB.y));
            Ah[1][kk][0] = pack2h(elu_f(xv2 * wA.x + bA.x),
                                  elu_f(xv2 * wA.y + bA.y));
            Ah[1][kk][1] = pack2h(elu_f(xv3 * wA.x + bA.x),
                                  elu_f(xv3 * wA.y + bA.y));
            Ah[1][kk][2] = pack2h(elu_f(xv2 * wB.x + bB.x),
                                  elu_f(xv2 * wB.y + bB.y));
            Ah[1][kk][3] = pack2h(elu_f(xv3 * wB.x + bB.x),
                                  elu_f(xv3 * wB.y + bB.y));
        }
    }

#pragma unroll 1
    for (int l = 0; l < NSTEP; l++) {
        if (l < 2) cp_wait1(); else cp_wait0();
        GBAR();   // slots: l=0 ->0, l=1 ->1, l=2 ->0

        const uint32_t* Wh =
            (const uint32_t*)(wgen + (l == 1 ? 32768 : 0)) + lane * 4;

        uint32_t Ahn[2][8][4];

        // ---- GEMM in two N-halves; pipelined LDS.128, 4 HMMAs per load ----
#pragma unroll
        for (int h = 0; h < 2; h++) {
            const uint32_t* Whh = Wh + h * 512;
            // bias-initialized half-N accumulators
            float acc[2][8][4];
            {
                const float* sb = sbias + l * 128 + 64 * h;
#pragma unroll
                for (int nt = 0; nt < 8; nt++) {
                    float2 b = *(const float2*)&sb[8 * nt + t2];
                    acc[0][nt][0] = b.x; acc[0][nt][1] = b.y;
                    acc[0][nt][2] = b.x; acc[0][nt][3] = b.y;
                    acc[1][nt][0] = b.x; acc[1][nt][1] = b.y;
                    acc[1][nt][2] = b.x; acc[1][nt][3] = b.y;
                }
            }
            // 32 loads, software-pipelined distance 1
            {
                uint4 w = *(const uint4*)(Whh);
#pragma unroll
                for (int q = 0; q < 32; q++) {
                    const int ks = q >> 2, p = q & 3;
                    uint4 wn;
                    if (q < 31) {
                        const int q1 = q + 1;
                        wn = *(const uint4*)(Whh + (q1 >> 2) * 1024 +
                                             (q1 & 3) * 128);
                    }
                    mma16816(acc[0][2 * p],     Ah[0][ks], w.x, w.y);
                    mma16816(acc[0][2 * p + 1], Ah[0][ks], w.z, w.w);
                    mma16816(acc[1][2 * p],     Ah[1][ks], w.x, w.y);
                    mma16816(acc[1][2 * p + 1], Ah[1][ks], w.z, w.w);
                    w = wn;
                }
            }

            if (l < 2) {
                // ELU + fp16 pack -> next A frags (kk = 4h..4h+3); bias already in
#pragma unroll
                for (int kk2 = 0; kk2 < 4; kk2++) {
                    const int nt0 = 2 * kk2, nt1 = 2 * kk2 + 1;
#pragma unroll
                    for (int m = 0; m < 2; m++) {
                        Ahn[m][4 * h + kk2][0] =
                            pack2h(elu_f(acc[m][nt0][0]), elu_f(acc[m][nt0][1]));
                        Ahn[m][4 * h + kk2][1] =
                            pack2h(elu_f(acc[m][nt0][2]), elu_f(acc[m][nt0][3]));
                        Ahn[m][4 * h + kk2][2] =
                            pack2h(elu_f(acc[m][nt1][0]), elu_f(acc[m][nt1][1]));
                        Ahn[m][4 * h + kk2][3] =
                            pack2h(elu_f(acc[m][nt1][2]), elu_f(acc[m][nt1][3]));
                    }
                }
            } else {
                // layer-4 half: backbone reduction + collapsed head (bias in acc)
#pragma unroll
                for (int nt = 0; nt < 8; nt++) {
                    const int col = 64 * h + 8 * nt + t2;
                    float a00 = acc[0][nt][0], a01 = acc[0][nt][1];
                    float a10 = acc[0][nt][2], a11 = acc[0][nt][3];
                    float a20 = acc[1][nt][0], a21 = acc[1][nt][1];
                    float a30 = acc[1][nt][2], a31 = acc[1][nt][3];
                    red2(&out[(long)(gr0)      * H_SZ + col], a00, a01);
                    red2(&out[(long)(gr0 + 8)  * H_SZ + col], a10, a11);
                    red2(&out[(long)(gr0 + 16) * H_SZ + col], a20, a21);
                    red2(&out[(long)(gr0 + 24) * H_SZ + col], a30, a31);
                    float2 wv0 = *(const float2*)&swv[ta0 * H_SZ + col];
                    float2 wv1 = *(const float2*)&swv[ta1 * H_SZ + col];
                    float2 wv2 = *(const float2*)&swv[ta2 * H_SZ + col];
                    float2 wv3 = *(const float2*)&swv[ta3 * H_SZ + col];
                    y0 += a00 * wv0.x + a01 * wv0.y;
                    y1 += a10 * wv1.x + a11 * wv1.y;
                    y2 += a20 * wv2.x + a21 * wv2.y;
                    y3 += a30 * wv3.x + a31 * wv3.y;
                }
            }
        }

        // post-GEMM barrier + prefetch only needed before slot0 reuse (l==0)
        if (l == 0) {
            GBAR();
            issue_w(wgbase, (const char*)&g_wp[2][f][0], gt);
        }

        if (l < 2) {
#pragma unroll
            for (int m = 0; m < 2; m++)
#pragma unroll
                for (int kk = 0; kk < 8; kk++) {
                    Ah[m][kk][0] = Ahn[m][kk][0];
                    Ah[m][kk][1] = Ahn[m][kk][1];
                    Ah[m][kk][2] = Ahn[m][kk][2];
                    Ah[m][kk][3] = Ahn[m][kk][3];
                }
        }
    }

    // ---- finale: head outputs ----
    y0 += __shfl_xor_sync(0xffffffffu, y0, 1);
    y0 += __shfl_xor_sync(0xffffffffu, y0, 2);
    y1 += __shfl_xor_sync(0xffffffffu, y1, 1);
    y1 += __shfl_xor_sync(0xffffffffu, y1, 2);
    y2 += __shfl_xor_sync(0xffffffffu, y2, 1);
    y2 += __shfl_xor_sync(0xffffffffu, y2, 2);
    y3 += __shfl_xor_sync(0xffffffffu, y3, 1);
    y3 += __shfl_xor_sync(0xffffffffu, y3, 2);
    if (t == 0) {
        atomicAdd(&out[B_SZ * H_SZ + gr0],      y0 + sc[ta0]);
        atomicAdd(&out[B_SZ * H_SZ + gr0 + 8],  y1 + sc[ta1]);
        atomicAdd(&out[B_SZ * H_SZ + gr0 + 16], y2 + sc[ta2]);
        atomicAdd(&out[B_SZ * H_SZ + gr0 + 24], y3 + sc[ta3]);
    }
}

// ---------------- launch ----------------
extern "C" void kernel_launch(void* const* d_in, const int* in_sizes, int n_in,
                              void* d_out, int out_size) {
    const float* x   = (const float*)d_in[0];
    const int*   a   = (const int*)d_in[1];
    const float* W1  = (const float*)d_in[2];
    const float* b1  = (const float*)d_in[3];
    const float* W2  = (const float*)d_in[4];
    const float* b2  = (const float*)d_in[5];
    const float* W3  = (const float*)d_in[6];
    const float* b3  = (const float*)d_in[7];
    const float* W4  = (const float*)d_in[8];
    const float* b4  = (const float*)d_in[9];
    const float* Wh1 = (const float*)d_in[10];
    const float* bh1 = (const float*)d_in[11];
    const float* Wh2 = (const float*)d_in[12];
    const float* bh2 = (const float*)d_in[13];
    float* out = (float*)d_out;

    cudaFuncSetAttribute(nam_main, cudaFuncAttributeMaxDynamicSharedMemorySize,
                         SMEM_BYTES);

    const int zero_blocks = (out_size + THREADS - 1) / THREADS;
    nam_setup<<<3 * F_SZ + F_SZ * T_SZ + zero_blocks, THREADS>>>(
        out, out_size, W2, W3, W4, Wh1, bh1, Wh2, bh2);

    dim3 grid(B_SZ / TB, F_SZ / 2);
    nam_main<<<grid, THREADS, SMEM_BYTES>>>(x, a, W1, b1, b2, b3, b4, out);
}